// round 7
// baseline (speedup 1.0000x reference)
#include <cuda_runtime.h>

#define NB    2048
#define NE    30
#define NA    38
#define NN    8
#define BASIS 32
#define KD    64
#define ED    128
#define HK    45
#define HO    91
#define HOP   96
#define NL    3

typedef unsigned long long ull;
typedef unsigned int uint32;

__device__ float g_xs [NB * NE * ED];
__device__ float g_msg[NB * NE * KD];

__device__ __forceinline__ float ssp(float x) {
    float t = __expf(-fabsf(x));
    return fmaxf(x, 0.f) + __logf(1.f + t) - 0.69314718055994530942f;
}
__device__ __forceinline__ ull ffma2(ull a, ull b, ull c) {
    ull d; asm("fma.rn.f32x2 %0, %1, %2, %3;" : "=l"(d) : "l"(a), "l"(b), "l"(c));
    return d;
}
__device__ __forceinline__ ull pack2(float x, float y) {
    ull r; asm("mov.b64 %0, {%1, %2};" : "=l"(r) : "f"(x), "f"(y)); return r;
}
__device__ __forceinline__ ull dup2(float x) { return pack2(x, x); }
__device__ __forceinline__ float2 unpack2(ull v) {
    float2 r; asm("mov.b64 {%0, %1}, %2;" : "=f"(r.x), "=f"(r.y) : "l"(v)); return r;
}
__device__ __forceinline__ ull ldsu64(const float* p) {
    return *reinterpret_cast<const ull*>(p);
}
__device__ __forceinline__ void sts2(float* p, float x, float y) {
    *reinterpret_cast<float2*>(p) = make_float2(x, y);
}
__device__ __forceinline__ uint32 f2tf(float x) {
    uint32 u; asm("cvt.rna.tf32.f32 %0, %1;" : "=r"(u) : "f"(x)); return u;
}
__device__ __forceinline__ void mma8(float& d0, float& d1, float& d2, float& d3,
                                     uint32 a0, uint32 a1, uint32 a2, uint32 a3,
                                     uint32 b0, uint32 b1) {
    asm volatile(
        "mma.sync.aligned.m16n8k8.row.col.f32.tf32.tf32.f32 "
        "{%0,%1,%2,%3},{%4,%5,%6,%7},{%8,%9},{%0,%1,%2,%3};"
        : "+f"(d0), "+f"(d1), "+f"(d2), "+f"(d3)
        : "r"(a0), "r"(a1), "r"(a2), "r"(a3), "r"(b0), "r"(b1));
}

__global__ void k_init(const float* __restrict__ emb_elec) {
    const int total = NB * NE * ED;
    for (int idx = blockIdx.x * blockDim.x + threadIdx.x; idx < total;
         idx += gridDim.x * blockDim.x) {
        int d = idx % ED, i = (idx / ED) % NE;
        g_xs[idx] = emb_elec[i * ED + d];
    }
}

// ---------------------------------------------------------------------------
// k_msg smem (floats):
//   zsv    [0,3456)       zs[j][c], j 0..47 (38..47 zero), stride 72
//   scratch[3456,15488)
//     phase1: eiwv 8192 @3456 | xs2 3840 @11648
//     phase2: B2f uint2[8*6*32] (3072 f) @3456 | H per warp 16x52 @+3072 (+w*832)
//   sb1 [15488,15536) | sb2 [15536,15600)
// ---------------------------------------------------------------------------
#define MS_TOTAL_F 15600
#define MS_BYTES   (MS_TOTAL_F * 4)

__global__ void __launch_bounds__(256) k_msg(const float* __restrict__ dists,
                                             const float* __restrict__ emb_nuc,
                                             const float* __restrict__ eiw,
                                             const float* __restrict__ kw1,
                                             const float* __restrict__ kb1,
                                             const float* __restrict__ kw2,
                                             const float* __restrict__ kb2, int l) {
    extern __shared__ float sm[];
    float*  zsv     = sm;                    // 48 x stride 72
    float*  scratch = sm + 3456;
    float*  eiwv    = scratch;               // phase 1
    float*  xs2     = scratch + 8192;        // phase 1
    uint2*  B2f     = reinterpret_cast<uint2*>(scratch);          // phase 2: 1536 uint2
    uint32* Hall    = reinterpret_cast<uint32*>(scratch) + 3072;  // phase 2
    float*  sb1     = sm + 15488;
    float*  sb2     = sm + 15536;

    const int b = blockIdx.x, tid = threadIdx.x;
    const int w = tid >> 5, lane = tid & 31;
    const int g = lane >> 2, t = lane & 3;

    // ---- phase 1a: stage eiw + xs, nuclear zs, zero pad rows ----
    {
        const float* W = eiw + (size_t)l * ED * KD;
        for (int it = tid; it < ED * 32; it += 256) {
            int q = it >> 5, c = it & 31;
            sts2(eiwv + 2 * it, W[q * KD + c], W[q * KD + c + 32]);
        }
        const float* xsb = g_xs + (size_t)b * NE * ED;
        for (int it = tid; it < 15 * ED; it += 256) {
            int p = it >> 7, q = it & 127;
            sts2(xs2 + 2 * it, xsb[(2 * p) * ED + q], xsb[(2 * p + 1) * ED + q]);
        }
        for (int idx = tid; idx < NN * KD; idx += 256) {
            int n = idx >> 6, c = idx & 63;
            zsv[(NE + n) * 72 + c] = emb_nuc[n * KD + c];
        }
        for (int idx = tid; idx < 10 * 64; idx += 256) {
            int r = idx >> 6, c = idx & 63;
            zsv[(38 + r) * 72 + c] = 0.f;
        }
    }
    __syncthreads();

    // ---- phase 1b: electron zs = xs @ eiw (f32x2 over electron pairs) ----
    for (int p = w; p < 15; p += 8) {
        ull acc0 = 0ull, acc1 = 0ull;
        const float* xrow = xs2 + p * 256;
        #pragma unroll 8
        for (int q = 0; q < ED; ++q) {
            ull x2 = ldsu64(xrow + 2 * q);
            float2 wf = unpack2(ldsu64(eiwv + (q * 32 + lane) * 2));
            acc0 = ffma2(x2, dup2(wf.x), acc0);
            acc1 = ffma2(x2, dup2(wf.y), acc1);
        }
        float2 a0 = unpack2(acc0), a1 = unpack2(acc1);
        zsv[(2 * p) * 72 + lane]          = a0.x;
        zsv[(2 * p + 1) * 72 + lane]      = a0.y;
        zsv[(2 * p) * 72 + lane + 32]     = a1.x;
        zsv[(2 * p + 1) * 72 + lane + 32] = a1.y;
    }
    __syncthreads();

    // ---- phase 2a: prepack w2 fragments (fragment-order uint2) + biases ----
    {
        const float* w2 = kw2 + (size_t)l * HK * KD;
        const float* b1 = kb1 + (size_t)l * HK;
        const float* b2 = kb2 + (size_t)l * KD;
        for (int it = tid; it < 8 * 6 * 32; it += 256) {
            int lane_ = it & 31;
            int kt = (it >> 5) % 6;
            int nt = it / 192;
            int g_ = lane_ >> 2, t_ = lane_ & 3;
            int n  = nt * 8 + g_;
            int k0 = kt * 8 + t_, k1 = k0 + 4;
            uint32 lo = f2tf((k0 < HK) ? w2[k0 * KD + n] : 0.f);
            uint32 hi = f2tf((k1 < HK) ? w2[k1 * KD + n] : 0.f);
            B2f[it] = make_uint2(lo, hi);
        }
        if (tid < 48) sb1[tid] = (tid < HK) ? b1[tid] : 0.f;
        if (tid < 64) sb2[tid] = b2[tid];
    }
    __syncthreads();

    // ---- hoist w1 B-fragments into 48 persistent registers ----
    uint32 B1r[6][4][2];
    {
        const float* w1 = kw1 + (size_t)l * BASIS * HK;
        #pragma unroll
        for (int nt = 0; nt < 6; ++nt) {
            int n = nt * 8 + g;
            bool ok = (n < HK);
            #pragma unroll
            for (int kt = 0; kt < 4; ++kt) {
                int k0 = kt * 8 + t;
                B1r[nt][kt][0] = f2tf(ok ? __ldg(w1 + k0 * HK + n) : 0.f);
                B1r[nt][kt][1] = f2tf(ok ? __ldg(w1 + (k0 + 4) * HK + n) : 0.f);
            }
        }
    }

    uint32* Hw = Hall + w * 832;   // 16 rows x stride 52

    // ---- main: warp w handles electrons i = w, w+8, ... ----
    for (int i = w; i < NE; i += 8) {
        const float* dbase = dists + ((size_t)(b * NE + i)) * NA * BASIS;
        float macc[16];
        #pragma unroll
        for (int r = 0; r < 16; ++r) macc[r] = 0.f;

        #pragma unroll
        for (int mt = 0; mt < 3; ++mt) {
            const int j0 = mt * 16 + g, j1 = j0 + 8;

            // A1 fragments straight from global (pad rows -> 0)
            uint32 A1[4][4];
            #pragma unroll
            for (int kt = 0; kt < 4; ++kt) {
                int k0 = kt * 8 + t;
                float a0 = (j0 < NA) ? __ldg(dbase + j0 * BASIS + k0) : 0.f;
                float a1 = (j1 < NA) ? __ldg(dbase + j1 * BASIS + k0) : 0.f;
                float a2 = (j0 < NA) ? __ldg(dbase + j0 * BASIS + k0 + 4) : 0.f;
                float a3 = (j1 < NA) ? __ldg(dbase + j1 * BASIS + k0 + 4) : 0.f;
                A1[kt][0] = f2tf(a0); A1[kt][1] = f2tf(a1);
                A1[kt][2] = f2tf(a2); A1[kt][3] = f2tf(a3);
            }

            // GEMM1 (B from registers) + ssp -> H
            #pragma unroll
            for (int nt = 0; nt < 6; ++nt) {
                float2 bb = *reinterpret_cast<const float2*>(sb1 + nt * 8 + 2 * t);
                float d0 = bb.x, d1 = bb.y, d2 = bb.x, d3 = bb.y;
                #pragma unroll
                for (int kt = 0; kt < 4; ++kt) {
                    mma8(d0, d1, d2, d3,
                         A1[kt][0], A1[kt][1], A1[kt][2], A1[kt][3],
                         B1r[nt][kt][0], B1r[nt][kt][1]);
                }
                uint2 lo = make_uint2(f2tf(ssp(d0)), f2tf(ssp(d1)));
                uint2 hi = make_uint2(f2tf(ssp(d2)), f2tf(ssp(d3)));
                *reinterpret_cast<uint2*>(Hw + g * 52 + nt * 8 + 2 * t)       = lo;
                *reinterpret_cast<uint2*>(Hw + (g + 8) * 52 + nt * 8 + 2 * t) = hi;
            }
            __syncwarp();

            // A2 fragments from H
            uint32 A2[6][4];
            #pragma unroll
            for (int kt = 0; kt < 6; ++kt) {
                A2[kt][0] = Hw[g * 52 + kt * 8 + t];
                A2[kt][1] = Hw[(g + 8) * 52 + kt * 8 + t];
                A2[kt][2] = Hw[g * 52 + kt * 8 + t + 4];
                A2[kt][3] = Hw[(g + 8) * 52 + kt * 8 + t + 4];
            }
            const float pm0 = (j0 != i) ? 1.f : 0.f;
            const float pm1 = (j1 != i) ? 1.f : 0.f;

            // GEMM2 (B via single LDS.64 per mma) + zs multiply + accumulate
            #pragma unroll
            for (int nt = 0; nt < 8; ++nt) {
                float2 bb = *reinterpret_cast<const float2*>(sb2 + nt * 8 + 2 * t);
                float d0 = bb.x, d1 = bb.y, d2 = bb.x, d3 = bb.y;
                const uint2* bp = B2f + nt * 192 + lane;
                #pragma unroll
                for (int kt = 0; kt < 6; ++kt) {
                    uint2 bf = bp[kt * 32];
                    mma8(d0, d1, d2, d3,
                         A2[kt][0], A2[kt][1], A2[kt][2], A2[kt][3],
                         bf.x, bf.y);
                }
                float2 z0 = *reinterpret_cast<const float2*>(zsv + j0 * 72 + nt * 8 + 2 * t);
                float2 z1 = *reinterpret_cast<const float2*>(zsv + j1 * 72 + nt * 8 + 2 * t);
                macc[2 * nt]     += pm0 * d0 * z0.x + pm1 * d2 * z1.x;
                macc[2 * nt + 1] += pm0 * d1 * z0.y + pm1 * d3 * z1.y;
            }
            __syncwarp();
        }

        // butterfly reduce over the 8 row-groups (lane/4)
        #pragma unroll
        for (int r = 0; r < 16; ++r) {
            macc[r] += __shfl_xor_sync(0xffffffffu, macc[r], 4);
            macc[r] += __shfl_xor_sync(0xffffffffu, macc[r], 8);
            macc[r] += __shfl_xor_sync(0xffffffffu, macc[r], 16);
        }
        if (g == 0) {
            float* mp = g_msg + ((size_t)(b * NE + i)) * KD;
            #pragma unroll
            for (int nt = 0; nt < 8; ++nt)
                *reinterpret_cast<float2*>(mp + nt * 8 + 2 * t) =
                    make_float2(macc[2 * nt], macc[2 * nt + 1]);
        }
    }
}

// ---------------------------------------------------------------------------
// k_out (unchanged — passing R4/R5 version)
// ---------------------------------------------------------------------------
#define VO_TOTAL_F 22144
#define VO_BYTES   (VO_TOTAL_F * 4)

__global__ void __launch_bounds__(256) k_out(const float* __restrict__ ow1,
                                             const float* __restrict__ ob1,
                                             const float* __restrict__ ow2,
                                             const float* __restrict__ ob2,
                                             int l, float* __restrict__ xs_out) {
    extern __shared__ float smo[];
    float* smsg2 = smo;
    float* sw1d  = smo + 1920;
    float* sw2d  = smo + 8064;
    float* sb1   = smo + 20352;
    float* sb2   = smo + 20480;
    float* sh2a  = smo + 20608;

    const int b = blockIdx.x, tid = threadIdx.x;
    const int w = tid >> 5, lane = tid & 31;
    const float* W1 = ow1 + (size_t)l * KD * HO;
    const float* B1 = ob1 + (size_t)l * HO;
    const float* W2 = ow2 + (size_t)l * HO * ED;
    const float* B2 = ob2 + (size_t)l * ED;

    {
        const float* mg = g_msg + (size_t)b * NE * KD;
        for (int it = tid; it < 15 * KD; it += 256) {
            int p = it >> 6, q = it & 63;
            sts2(smsg2 + 2 * it, mg[(2 * p) * KD + q], mg[(2 * p + 1) * KD + q]);
        }
        for (int it = tid; it < KD * 48; it += 256) {
            int q = it / 48, c = it % 48;
            float x = (c < HO) ? W1[q * HO + c] : 0.f;
            float y = (c + 48 < HO) ? W1[q * HO + c + 48] : 0.f;
            sts2(sw1d + 2 * it, x, y);
        }
        for (int it = tid; it < HOP * 64; it += 256) {
            int k = it >> 6, c = it & 63;
            float x = (k < HO) ? W2[k * ED + c] : 0.f;
            float y = (k < HO) ? W2[k * ED + c + 64] : 0.f;
            sts2(sw2d + 2 * it, x, y);
        }
        for (int it = tid; it < 128; it += 256) {
            sb1[it] = (it < HO) ? B1[it] : 0.f;
            sb2[it] = B2[it];
        }
    }
    __syncthreads();

    const ull bA0x = dup2(sb1[lane]);
    const ull bA0y = dup2(sb1[lane + 48]);
    const ull bA1x = dup2(sb1[lane + 32]);
    const ull bA1y = dup2(sb1[lane + 80]);
    const ull bC0 = dup2(sb2[lane]);
    const ull bC1 = dup2(sb2[lane + 32]);
    const ull bC2 = dup2(sb2[lane + 64]);
    const ull bC3 = dup2(sb2[lane + 96]);

    float* sh2 = sh2a + w * 192;

    for (int p = w; p < 15; p += 8) {
        ull A0x = bA0x, A0y = bA0y, A1x = bA1x, A1y = bA1y;
        const float* mrow = smsg2 + p * 128;
        #pragma unroll
        for (int q = 0; q < KD; ++q) {
            ull m2 = ldsu64(mrow + 2 * q);
            float2 w0 = unpack2(ldsu64(sw1d + (q * 48 + lane) * 2));
            float2 w1f = unpack2(ldsu64(sw1d + (q * 48 + lane + 32) * 2));
            A0x = ffma2(m2, dup2(w0.x), A0x);
            A0y = ffma2(m2, dup2(w0.y), A0y);
            A1x = ffma2(m2, dup2(w1f.x), A1x);
            A1y = ffma2(m2, dup2(w1f.y), A1y);
        }
        {
            float2 tv;
            tv = unpack2(A0x); sts2(sh2 + (lane) * 2,      ssp(tv.x), ssp(tv.y));
            tv = unpack2(A0y); sts2(sh2 + (lane + 48) * 2, ssp(tv.x), ssp(tv.y));
            if (lane < 16) {
                tv = unpack2(A1x); sts2(sh2 + (lane + 32) * 2, ssp(tv.x), ssp(tv.y));
                tv = unpack2(A1y); sts2(sh2 + (lane + 80) * 2, ssp(tv.x), ssp(tv.y));
            }
        }
        __syncwarp();

        ull C0 = bC0, C1 = bC1, C2 = bC2, C3 = bC3;
        #pragma unroll
        for (int k = 0; k < HOP; ++k) {
            ull h2 = ldsu64(sh2 + 2 * k);
            float2 w0 = unpack2(ldsu64(sw2d + (k * 64 + lane) * 2));
            float2 w1f = unpack2(ldsu64(sw2d + (k * 64 + lane + 32) * 2));
            C0 = ffma2(h2, dup2(w0.x), C0);
            C2 = ffma2(h2, dup2(w0.y), C2);
            C1 = ffma2(h2, dup2(w1f.x), C1);
            C3 = ffma2(h2, dup2(w1f.y), C3);
        }
        __syncwarp();

        int i0 = 2 * p, i1 = 2 * p + 1;
        size_t b0 = ((size_t)(b * NE + i0)) * ED;
        size_t b1o = ((size_t)(b * NE + i1)) * ED;
        float2 c0 = unpack2(C0), c1 = unpack2(C1), c2 = unpack2(C2), c3 = unpack2(C3);
        xs_out[b0 + lane]       = g_xs[b0 + lane]       + c0.x;
        xs_out[b0 + lane + 32]  = g_xs[b0 + lane + 32]  + c1.x;
        xs_out[b0 + lane + 64]  = g_xs[b0 + lane + 64]  + c2.x;
        xs_out[b0 + lane + 96]  = g_xs[b0 + lane + 96]  + c3.x;
        xs_out[b1o + lane]      = g_xs[b1o + lane]      + c0.y;
        xs_out[b1o + lane + 32] = g_xs[b1o + lane + 32] + c1.y;
        xs_out[b1o + lane + 64] = g_xs[b1o + lane + 64] + c2.y;
        xs_out[b1o + lane + 96] = g_xs[b1o + lane + 96] + c3.y;
    }
}

// ---------------------------------------------------------------------------
extern "C" void kernel_launch(void* const* d_in, const int* in_sizes, int n_in,
                              void* d_out, int out_size) {
    const float* dists    = (const float*)d_in[0];
    const float* emb_elec = (const float*)d_in[1];
    const float* emb_nuc  = (const float*)d_in[2];
    const float* kw1      = (const float*)d_in[3];
    const float* kb1      = (const float*)d_in[4];
    const float* kw2      = (const float*)d_in[5];
    const float* kb2      = (const float*)d_in[6];
    const float* eiw      = (const float*)d_in[7];
    const float* ow1      = (const float*)d_in[8];
    const float* ob1      = (const float*)d_in[9];
    const float* ow2      = (const float*)d_in[10];
    const float* ob2      = (const float*)d_in[11];
    float* out = (float*)d_out;

    static int configured = 0;
    if (!configured) {
        cudaFuncSetAttribute(k_msg, cudaFuncAttributeMaxDynamicSharedMemorySize, MS_BYTES);
        cudaFuncSetAttribute(k_out, cudaFuncAttributeMaxDynamicSharedMemorySize, VO_BYTES);
        configured = 1;
    }
    void* xsptr = nullptr;
    cudaGetSymbolAddress(&xsptr, g_xs);

    k_init<<<4096, 256>>>(emb_elec);
    for (int l = 0; l < NL; ++l) {
        k_msg<<<NB, 256, MS_BYTES>>>(dists, emb_nuc, eiw, kw1, kb1, kw2, kb2, l);
        float* xs_out = (l == NL - 1) ? out : (float*)xsptr;
        k_out<<<NB, 256, VO_BYTES>>>(ow1, ob1, ow2, ob2, l, xs_out);
    }
}

// round 8
// speedup vs baseline: 1.4064x; 1.4064x over previous
#include <cuda_runtime.h>

#define NB    2048
#define NE    30
#define NA    38
#define NN    8
#define BASIS 32
#define KD    64
#define ED    128
#define HK    45
#define HO    91
#define HOP   96
#define NL    3

typedef unsigned long long ull;
typedef unsigned int uint32;

__device__ float g_xs [NB * NE * ED];
__device__ float g_msg[NB * NE * KD];

__device__ __forceinline__ float ssp(float x) {
    float t = __expf(-fabsf(x));
    return fmaxf(x, 0.f) + __logf(1.f + t) - 0.69314718055994530942f;
}
__device__ __forceinline__ ull ffma2(ull a, ull b, ull c) {
    ull d; asm("fma.rn.f32x2 %0, %1, %2, %3;" : "=l"(d) : "l"(a), "l"(b), "l"(c));
    return d;
}
__device__ __forceinline__ ull pack2(float x, float y) {
    ull r; asm("mov.b64 %0, {%1, %2};" : "=l"(r) : "f"(x), "f"(y)); return r;
}
__device__ __forceinline__ ull dup2(float x) { return pack2(x, x); }
__device__ __forceinline__ float2 unpack2(ull v) {
    float2 r; asm("mov.b64 {%0, %1}, %2;" : "=f"(r.x), "=f"(r.y) : "l"(v)); return r;
}
__device__ __forceinline__ ull ldsu64(const float* p) {
    return *reinterpret_cast<const ull*>(p);
}
__device__ __forceinline__ void sts2(float* p, float x, float y) {
    *reinterpret_cast<float2*>(p) = make_float2(x, y);
}
__device__ __forceinline__ uint32 f2tf(float x) {
    uint32 u; asm("cvt.rna.tf32.f32 %0, %1;" : "=r"(u) : "f"(x)); return u;
}
__device__ __forceinline__ void mma8(float& d0, float& d1, float& d2, float& d3,
                                     uint32 a0, uint32 a1, uint32 a2, uint32 a3,
                                     uint32 b0, uint32 b1) {
    asm volatile(
        "mma.sync.aligned.m16n8k8.row.col.f32.tf32.tf32.f32 "
        "{%0,%1,%2,%3},{%4,%5,%6,%7},{%8,%9},{%0,%1,%2,%3};"
        : "+f"(d0), "+f"(d1), "+f"(d2), "+f"(d3)
        : "r"(a0), "r"(a1), "r"(a2), "r"(a3), "r"(b0), "r"(b1));
}

__global__ void k_init(const float* __restrict__ emb_elec) {
    const int total = NB * NE * ED;
    for (int idx = blockIdx.x * blockDim.x + threadIdx.x; idx < total;
         idx += gridDim.x * blockDim.x) {
        int d = idx % ED, i = (idx / ED) % NE;
        g_xs[idx] = emb_elec[i * ED + d];
    }
}

// ---------------------------------------------------------------------------
// k_msg smem (floats):
//   zsv    [0,3456)       zs[j][c], j 0..47 (38..47 zero), stride 72
//   scratch[3456,15488)   (12032 floats)
//     phase1: eiwv 8192 @scratch | xs2 3840 @scratch+8192
//     phase2: B1f uint2[6*4*32]  (1536 f) @scratch
//             B2f uint2[8*6*32]  (3072 f) @scratch+1536
//             H per warp 16x52 (832 f)    @scratch+4608 (+w*832)
//   sb1 [15488,15536) | sb2 [15536,15600)
// ---------------------------------------------------------------------------
#define MS_TOTAL_F 15600
#define MS_BYTES   (MS_TOTAL_F * 4)

__global__ void __launch_bounds__(256) k_msg(const float* __restrict__ dists,
                                             const float* __restrict__ emb_nuc,
                                             const float* __restrict__ eiw,
                                             const float* __restrict__ kw1,
                                             const float* __restrict__ kb1,
                                             const float* __restrict__ kw2,
                                             const float* __restrict__ kb2, int l) {
    extern __shared__ float sm[];
    float*  zsv     = sm;                    // 48 x stride 72
    float*  scratch = sm + 3456;
    float*  eiwv    = scratch;               // phase 1
    float*  xs2     = scratch + 8192;        // phase 1
    uint2*  B1f     = reinterpret_cast<uint2*>(scratch);           // phase 2: 768 uint2
    uint2*  B2f     = reinterpret_cast<uint2*>(scratch + 1536);    // phase 2: 1536 uint2
    uint32* Hall    = reinterpret_cast<uint32*>(scratch + 4608);   // phase 2
    float*  sb1     = sm + 15488;
    float*  sb2     = sm + 15536;

    const int b = blockIdx.x, tid = threadIdx.x;
    const int w = tid >> 5, lane = tid & 31;
    const int g = lane >> 2, t = lane & 3;

    // ---- phase 1a: stage eiw + xs, nuclear zs, zero pad rows ----
    {
        const float* W = eiw + (size_t)l * ED * KD;
        for (int it = tid; it < ED * 32; it += 256) {
            int q = it >> 5, c = it & 31;
            sts2(eiwv + 2 * it, W[q * KD + c], W[q * KD + c + 32]);
        }
        const float* xsb = g_xs + (size_t)b * NE * ED;
        for (int it = tid; it < 15 * ED; it += 256) {
            int p = it >> 7, q = it & 127;
            sts2(xs2 + 2 * it, xsb[(2 * p) * ED + q], xsb[(2 * p + 1) * ED + q]);
        }
        for (int idx = tid; idx < NN * KD; idx += 256) {
            int n = idx >> 6, c = idx & 63;
            zsv[(NE + n) * 72 + c] = emb_nuc[n * KD + c];
        }
        for (int idx = tid; idx < 10 * 64; idx += 256) {
            int r = idx >> 6, c = idx & 63;
            zsv[(38 + r) * 72 + c] = 0.f;
        }
    }
    __syncthreads();

    // ---- phase 1b: electron zs = xs @ eiw (f32x2 over electron pairs) ----
    for (int p = w; p < 15; p += 8) {
        ull acc0 = 0ull, acc1 = 0ull;
        const float* xrow = xs2 + p * 256;
        #pragma unroll 8
        for (int q = 0; q < ED; ++q) {
            ull x2 = ldsu64(xrow + 2 * q);
            float2 wf = unpack2(ldsu64(eiwv + (q * 32 + lane) * 2));
            acc0 = ffma2(x2, dup2(wf.x), acc0);
            acc1 = ffma2(x2, dup2(wf.y), acc1);
        }
        float2 a0 = unpack2(acc0), a1 = unpack2(acc1);
        zsv[(2 * p) * 72 + lane]          = a0.x;
        zsv[(2 * p + 1) * 72 + lane]      = a0.y;
        zsv[(2 * p) * 72 + lane + 32]     = a1.x;
        zsv[(2 * p + 1) * 72 + lane + 32] = a1.y;
    }
    __syncthreads();

    // ---- phase 2a: prepack w1/w2 fragments (fragment-order uint2) + biases ----
    {
        const float* w1 = kw1 + (size_t)l * BASIS * HK;
        const float* w2 = kw2 + (size_t)l * HK * KD;
        const float* b1 = kb1 + (size_t)l * HK;
        const float* b2 = kb2 + (size_t)l * KD;
        // B1f: [nt(6)][kt(4)][lane(32)], lane=(g,t): n=nt*8+g, k=kt*8+t
        for (int it = tid; it < 6 * 4 * 32; it += 256) {
            int lane_ = it & 31;
            int kt = (it >> 5) & 3;
            int nt = it >> 7;
            int g_ = lane_ >> 2, t_ = lane_ & 3;
            int n  = nt * 8 + g_;
            int k0 = kt * 8 + t_;
            bool ok = (n < HK);
            uint32 lo = f2tf(ok ? w1[k0 * HK + n] : 0.f);
            uint32 hi = f2tf(ok ? w1[(k0 + 4) * HK + n] : 0.f);
            B1f[it] = make_uint2(lo, hi);
        }
        // B2f: [nt(8)][kt(6)][lane(32)], lane=(g,t): n=nt*8+g, k=kt*8+t
        for (int it = tid; it < 8 * 6 * 32; it += 256) {
            int lane_ = it & 31;
            int kt = (it >> 5) % 6;
            int nt = it / 192;
            int g_ = lane_ >> 2, t_ = lane_ & 3;
            int n  = nt * 8 + g_;
            int k0 = kt * 8 + t_, k1 = k0 + 4;
            uint32 lo = f2tf((k0 < HK) ? w2[k0 * KD + n] : 0.f);
            uint32 hi = f2tf((k1 < HK) ? w2[k1 * KD + n] : 0.f);
            B2f[it] = make_uint2(lo, hi);
        }
        if (tid < 48) sb1[tid] = (tid < HK) ? b1[tid] : 0.f;
        if (tid < 64) sb2[tid] = b2[tid];
    }
    __syncthreads();

    uint32* Hw = Hall + w * 832;   // 16 rows x stride 52

    // ---- main: warp w handles electrons i = w, w+8, ... ----
    for (int i = w; i < NE; i += 8) {
        const float* dbase = dists + ((size_t)(b * NE + i)) * NA * BASIS;
        float macc[16];
        #pragma unroll
        for (int r = 0; r < 16; ++r) macc[r] = 0.f;

        #pragma unroll
        for (int mt = 0; mt < 3; ++mt) {
            const int j0 = mt * 16 + g, j1 = j0 + 8;

            // A1 fragments straight from global (pad rows -> 0)
            uint32 A1[4][4];
            #pragma unroll
            for (int kt = 0; kt < 4; ++kt) {
                int k0 = kt * 8 + t;
                float a0 = (j0 < NA) ? __ldg(dbase + j0 * BASIS + k0) : 0.f;
                float a1 = (j1 < NA) ? __ldg(dbase + j1 * BASIS + k0) : 0.f;
                float a2 = (j0 < NA) ? __ldg(dbase + j0 * BASIS + k0 + 4) : 0.f;
                float a3 = (j1 < NA) ? __ldg(dbase + j1 * BASIS + k0 + 4) : 0.f;
                A1[kt][0] = f2tf(a0); A1[kt][1] = f2tf(a1);
                A1[kt][2] = f2tf(a2); A1[kt][3] = f2tf(a3);
            }

            // GEMM1 (B via single LDS.64 per mma) + ssp -> H
            #pragma unroll
            for (int nt = 0; nt < 6; ++nt) {
                float2 bb = *reinterpret_cast<const float2*>(sb1 + nt * 8 + 2 * t);
                float d0 = bb.x, d1 = bb.y, d2 = bb.x, d3 = bb.y;
                const uint2* bp = B1f + nt * 128 + lane;
                #pragma unroll
                for (int kt = 0; kt < 4; ++kt) {
                    uint2 bf = bp[kt * 32];
                    mma8(d0, d1, d2, d3,
                         A1[kt][0], A1[kt][1], A1[kt][2], A1[kt][3],
                         bf.x, bf.y);
                }
                uint2 lo = make_uint2(f2tf(ssp(d0)), f2tf(ssp(d1)));
                uint2 hi = make_uint2(f2tf(ssp(d2)), f2tf(ssp(d3)));
                *reinterpret_cast<uint2*>(Hw + g * 52 + nt * 8 + 2 * t)       = lo;
                *reinterpret_cast<uint2*>(Hw + (g + 8) * 52 + nt * 8 + 2 * t) = hi;
            }
            __syncwarp();

            // A2 fragments from H
            uint32 A2[6][4];
            #pragma unroll
            for (int kt = 0; kt < 6; ++kt) {
                A2[kt][0] = Hw[g * 52 + kt * 8 + t];
                A2[kt][1] = Hw[(g + 8) * 52 + kt * 8 + t];
                A2[kt][2] = Hw[g * 52 + kt * 8 + t + 4];
                A2[kt][3] = Hw[(g + 8) * 52 + kt * 8 + t + 4];
            }
            const float pm0 = (j0 != i) ? 1.f : 0.f;
            const float pm1 = (j1 != i) ? 1.f : 0.f;

            // GEMM2 (B via single LDS.64 per mma) + zs multiply + accumulate
            #pragma unroll
            for (int nt = 0; nt < 8; ++nt) {
                float2 bb = *reinterpret_cast<const float2*>(sb2 + nt * 8 + 2 * t);
                float d0 = bb.x, d1 = bb.y, d2 = bb.x, d3 = bb.y;
                const uint2* bp = B2f + nt * 192 + lane;
                #pragma unroll
                for (int kt = 0; kt < 6; ++kt) {
                    uint2 bf = bp[kt * 32];
                    mma8(d0, d1, d2, d3,
                         A2[kt][0], A2[kt][1], A2[kt][2], A2[kt][3],
                         bf.x, bf.y);
                }
                float2 z0 = *reinterpret_cast<const float2*>(zsv + j0 * 72 + nt * 8 + 2 * t);
                float2 z1 = *reinterpret_cast<const float2*>(zsv + j1 * 72 + nt * 8 + 2 * t);
                macc[2 * nt]     += pm0 * d0 * z0.x + pm1 * d2 * z1.x;
                macc[2 * nt + 1] += pm0 * d1 * z0.y + pm1 * d3 * z1.y;
            }
            __syncwarp();
        }

        // butterfly reduce over the 8 row-groups (lane/4)
        #pragma unroll
        for (int r = 0; r < 16; ++r) {
            macc[r] += __shfl_xor_sync(0xffffffffu, macc[r], 4);
            macc[r] += __shfl_xor_sync(0xffffffffu, macc[r], 8);
            macc[r] += __shfl_xor_sync(0xffffffffu, macc[r], 16);
        }
        if (g == 0) {
            float* mp = g_msg + ((size_t)(b * NE + i)) * KD;
            #pragma unroll
            for (int nt = 0; nt < 8; ++nt)
                *reinterpret_cast<float2*>(mp + nt * 8 + 2 * t) =
                    make_float2(macc[2 * nt], macc[2 * nt + 1]);
        }
    }
}

// ---------------------------------------------------------------------------
// k_out (unchanged — passing R4/R5 version)
// ---------------------------------------------------------------------------
#define VO_TOTAL_F 22144
#define VO_BYTES   (VO_TOTAL_F * 4)

__global__ void __launch_bounds__(256) k_out(const float* __restrict__ ow1,
                                             const float* __restrict__ ob1,
                                             const float* __restrict__ ow2,
                                             const float* __restrict__ ob2,
                                             int l, float* __restrict__ xs_out) {
    extern __shared__ float smo[];
    float* smsg2 = smo;
    float* sw1d  = smo + 1920;
    float* sw2d  = smo + 8064;
    float* sb1   = smo + 20352;
    float* sb2   = smo + 20480;
    float* sh2a  = smo + 20608;

    const int b = blockIdx.x, tid = threadIdx.x;
    const int w = tid >> 5, lane = tid & 31;
    const float* W1 = ow1 + (size_t)l * KD * HO;
    const float* B1 = ob1 + (size_t)l * HO;
    const float* W2 = ow2 + (size_t)l * HO * ED;
    const float* B2 = ob2 + (size_t)l * ED;

    {
        const float* mg = g_msg + (size_t)b * NE * KD;
        for (int it = tid; it < 15 * KD; it += 256) {
            int p = it >> 6, q = it & 63;
            sts2(smsg2 + 2 * it, mg[(2 * p) * KD + q], mg[(2 * p + 1) * KD + q]);
        }
        for (int it = tid; it < KD * 48; it += 256) {
            int q = it / 48, c = it % 48;
            float x = (c < HO) ? W1[q * HO + c] : 0.f;
            float y = (c + 48 < HO) ? W1[q * HO + c + 48] : 0.f;
            sts2(sw1d + 2 * it, x, y);
        }
        for (int it = tid; it < HOP * 64; it += 256) {
            int k = it >> 6, c = it & 63;
            float x = (k < HO) ? W2[k * ED + c] : 0.f;
            float y = (k < HO) ? W2[k * ED + c + 64] : 0.f;
            sts2(sw2d + 2 * it, x, y);
        }
        for (int it = tid; it < 128; it += 256) {
            sb1[it] = (it < HO) ? B1[it] : 0.f;
            sb2[it] = B2[it];
        }
    }
    __syncthreads();

    const ull bA0x = dup2(sb1[lane]);
    const ull bA0y = dup2(sb1[lane + 48]);
    const ull bA1x = dup2(sb1[lane + 32]);
    const ull bA1y = dup2(sb1[lane + 80]);
    const ull bC0 = dup2(sb2[lane]);
    const ull bC1 = dup2(sb2[lane + 32]);
    const ull bC2 = dup2(sb2[lane + 64]);
    const ull bC3 = dup2(sb2[lane + 96]);

    float* sh2 = sh2a + w * 192;

    for (int p = w; p < 15; p += 8) {
        ull A0x = bA0x, A0y = bA0y, A1x = bA1x, A1y = bA1y;
        const float* mrow = smsg2 + p * 128;
        #pragma unroll
        for (int q = 0; q < KD; ++q) {
            ull m2 = ldsu64(mrow + 2 * q);
            float2 w0 = unpack2(ldsu64(sw1d + (q * 48 + lane) * 2));
            float2 w1f = unpack2(ldsu64(sw1d + (q * 48 + lane + 32) * 2));
            A0x = ffma2(m2, dup2(w0.x), A0x);
            A0y = ffma2(m2, dup2(w0.y), A0y);
            A1x = ffma2(m2, dup2(w1f.x), A1x);
            A1y = ffma2(m2, dup2(w1f.y), A1y);
        }
        {
            float2 tv;
            tv = unpack2(A0x); sts2(sh2 + (lane) * 2,      ssp(tv.x), ssp(tv.y));
            tv = unpack2(A0y); sts2(sh2 + (lane + 48) * 2, ssp(tv.x), ssp(tv.y));
            if (lane < 16) {
                tv = unpack2(A1x); sts2(sh2 + (lane + 32) * 2, ssp(tv.x), ssp(tv.y));
                tv = unpack2(A1y); sts2(sh2 + (lane + 80) * 2, ssp(tv.x), ssp(tv.y));
            }
        }
        __syncwarp();

        ull C0 = bC0, C1 = bC1, C2 = bC2, C3 = bC3;
        #pragma unroll
        for (int k = 0; k < HOP; ++k) {
            ull h2 = ldsu64(sh2 + 2 * k);
            float2 w0 = unpack2(ldsu64(sw2d + (k * 64 + lane) * 2));
            float2 w1f = unpack2(ldsu64(sw2d + (k * 64 + lane + 32) * 2));
            C0 = ffma2(h2, dup2(w0.x), C0);
            C2 = ffma2(h2, dup2(w0.y), C2);
            C1 = ffma2(h2, dup2(w1f.x), C1);
            C3 = ffma2(h2, dup2(w1f.y), C3);
        }
        __syncwarp();

        int i0 = 2 * p, i1 = 2 * p + 1;
        size_t b0 = ((size_t)(b * NE + i0)) * ED;
        size_t b1o = ((size_t)(b * NE + i1)) * ED;
        float2 c0 = unpack2(C0), c1 = unpack2(C1), c2 = unpack2(C2), c3 = unpack2(C3);
        xs_out[b0 + lane]       = g_xs[b0 + lane]       + c0.x;
        xs_out[b0 + lane + 32]  = g_xs[b0 + lane + 32]  + c1.x;
        xs_out[b0 + lane + 64]  = g_xs[b0 + lane + 64]  + c2.x;
        xs_out[b0 + lane + 96]  = g_xs[b0 + lane + 96]  + c3.x;
        xs_out[b1o + lane]      = g_xs[b1o + lane]      + c0.y;
        xs_out[b1o + lane + 32] = g_xs[b1o + lane + 32] + c1.y;
        xs_out[b1o + lane + 64] = g_xs[b1o + lane + 64] + c2.y;
        xs_out[b1o + lane + 96] = g_xs[b1o + lane + 96] + c3.y;
    }
}

// ---------------------------------------------------------------------------
extern "C" void kernel_launch(void* const* d_in, const int* in_sizes, int n_in,
                              void* d_out, int out_size) {
    const float* dists    = (const float*)d_in[0];
    const float* emb_elec = (const float*)d_in[1];
    const float* emb_nuc  = (const float*)d_in[2];
    const float* kw1      = (const float*)d_in[3];
    const float* kb1      = (const float*)d_in[4];
    const float* kw2      = (const float*)d_in[5];
    const float* kb2      = (const float*)d_in[6];
    const float* eiw      = (const float*)d_in[7];
    const float* ow1      = (const float*)d_in[8];
    const float* ob1      = (const float*)d_in[9];
    const float* ow2      = (const float*)d_in[10];
    const float* ob2      = (const float*)d_in[11];
    float* out = (float*)d_out;

    static int configured = 0;
    if (!configured) {
        cudaFuncSetAttribute(k_msg, cudaFuncAttributeMaxDynamicSharedMemorySize, MS_BYTES);
        cudaFuncSetAttribute(k_out, cudaFuncAttributeMaxDynamicSharedMemorySize, VO_BYTES);
        configured = 1;
    }
    void* xsptr = nullptr;
    cudaGetSymbolAddress(&xsptr, g_xs);

    k_init<<<4096, 256>>>(emb_elec);
    for (int l = 0; l < NL; ++l) {
        k_msg<<<NB, 256, MS_BYTES>>>(dists, emb_nuc, eiw, kw1, kb1, kw2, kb2, l);
        float* xs_out = (l == NL - 1) ? out : (float*)xsptr;
        k_out<<<NB, 256, VO_BYTES>>>(ow1, ob1, ow2, ob2, l, xs_out);
    }
}

// round 9
// speedup vs baseline: 1.6330x; 1.1611x over previous
#include <cuda_runtime.h>

#define NB    2048
#define NE    30
#define NA    38
#define NN    8
#define BASIS 32
#define KD    64
#define ED    128
#define HK    45
#define HO    91
#define NL    3

typedef unsigned long long ull;
typedef unsigned int uint32;

__device__ float g_xs [NB * NE * ED];
__device__ float g_msg[NB * NE * KD];

__device__ __forceinline__ float ssp(float x) {
    float t = __expf(-fabsf(x));
    return fmaxf(x, 0.f) + __logf(1.f + t) - 0.69314718055994530942f;
}
__device__ __forceinline__ ull ffma2(ull a, ull b, ull c) {
    ull d; asm("fma.rn.f32x2 %0, %1, %2, %3;" : "=l"(d) : "l"(a), "l"(b), "l"(c));
    return d;
}
__device__ __forceinline__ ull pack2(float x, float y) {
    ull r; asm("mov.b64 %0, {%1, %2};" : "=l"(r) : "f"(x), "f"(y)); return r;
}
__device__ __forceinline__ ull dup2(float x) { return pack2(x, x); }
__device__ __forceinline__ float2 unpack2(ull v) {
    float2 r; asm("mov.b64 {%0, %1}, %2;" : "=f"(r.x), "=f"(r.y) : "l"(v)); return r;
}
__device__ __forceinline__ ull ldsu64(const float* p) {
    return *reinterpret_cast<const ull*>(p);
}
__device__ __forceinline__ void sts2(float* p, float x, float y) {
    *reinterpret_cast<float2*>(p) = make_float2(x, y);
}
__device__ __forceinline__ uint32 f2tf(float x) {
    uint32 u; asm("cvt.rna.tf32.f32 %0, %1;" : "=r"(u) : "f"(x)); return u;
}
__device__ __forceinline__ void mma8(float& d0, float& d1, float& d2, float& d3,
                                     uint32 a0, uint32 a1, uint32 a2, uint32 a3,
                                     uint32 b0, uint32 b1) {
    asm volatile(
        "mma.sync.aligned.m16n8k8.row.col.f32.tf32.tf32.f32 "
        "{%0,%1,%2,%3},{%4,%5,%6,%7},{%8,%9},{%0,%1,%2,%3};"
        : "+f"(d0), "+f"(d1), "+f"(d2), "+f"(d3)
        : "r"(a0), "r"(a1), "r"(a2), "r"(a3), "r"(b0), "r"(b1));
}

__global__ void k_init(const float* __restrict__ emb_elec) {
    const int total = NB * NE * ED;
    for (int idx = blockIdx.x * blockDim.x + threadIdx.x; idx < total;
         idx += gridDim.x * blockDim.x) {
        int d = idx % ED, i = (idx / ED) % NE;
        g_xs[idx] = emb_elec[i * ED + d];
    }
}

// ---------------------------------------------------------------------------
// k_msg — unchanged from the R7 1565us version
// ---------------------------------------------------------------------------
#define MS_TOTAL_F 15600
#define MS_BYTES   (MS_TOTAL_F * 4)

__global__ void __launch_bounds__(256) k_msg(const float* __restrict__ dists,
                                             const float* __restrict__ emb_nuc,
                                             const float* __restrict__ eiw,
                                             const float* __restrict__ kw1,
                                             const float* __restrict__ kb1,
                                             const float* __restrict__ kw2,
                                             const float* __restrict__ kb2, int l) {
    extern __shared__ float sm[];
    float*  zsv     = sm;
    float*  scratch = sm + 3456;
    float*  eiwv    = scratch;
    float*  xs2     = scratch + 8192;
    uint2*  B1f     = reinterpret_cast<uint2*>(scratch);
    uint2*  B2f     = reinterpret_cast<uint2*>(scratch + 1536);
    uint32* Hall    = reinterpret_cast<uint32*>(scratch + 4608);
    float*  sb1     = sm + 15488;
    float*  sb2     = sm + 15536;

    const int b = blockIdx.x, tid = threadIdx.x;
    const int w = tid >> 5, lane = tid & 31;
    const int g = lane >> 2, t = lane & 3;

    {
        const float* W = eiw + (size_t)l * ED * KD;
        for (int it = tid; it < ED * 32; it += 256) {
            int q = it >> 5, c = it & 31;
            sts2(eiwv + 2 * it, W[q * KD + c], W[q * KD + c + 32]);
        }
        const float* xsb = g_xs + (size_t)b * NE * ED;
        for (int it = tid; it < 15 * ED; it += 256) {
            int p = it >> 7, q = it & 127;
            sts2(xs2 + 2 * it, xsb[(2 * p) * ED + q], xsb[(2 * p + 1) * ED + q]);
        }
        for (int idx = tid; idx < NN * KD; idx += 256) {
            int n = idx >> 6, c = idx & 63;
            zsv[(NE + n) * 72 + c] = emb_nuc[n * KD + c];
        }
        for (int idx = tid; idx < 10 * 64; idx += 256) {
            int r = idx >> 6, c = idx & 63;
            zsv[(38 + r) * 72 + c] = 0.f;
        }
    }
    __syncthreads();

    for (int p = w; p < 15; p += 8) {
        ull acc0 = 0ull, acc1 = 0ull;
        const float* xrow = xs2 + p * 256;
        #pragma unroll 8
        for (int q = 0; q < ED; ++q) {
            ull x2 = ldsu64(xrow + 2 * q);
            float2 wf = unpack2(ldsu64(eiwv + (q * 32 + lane) * 2));
            acc0 = ffma2(x2, dup2(wf.x), acc0);
            acc1 = ffma2(x2, dup2(wf.y), acc1);
        }
        float2 a0 = unpack2(acc0), a1 = unpack2(acc1);
        zsv[(2 * p) * 72 + lane]          = a0.x;
        zsv[(2 * p + 1) * 72 + lane]      = a0.y;
        zsv[(2 * p) * 72 + lane + 32]     = a1.x;
        zsv[(2 * p + 1) * 72 + lane + 32] = a1.y;
    }
    __syncthreads();

    {
        const float* w1 = kw1 + (size_t)l * BASIS * HK;
        const float* w2 = kw2 + (size_t)l * HK * KD;
        const float* b1 = kb1 + (size_t)l * HK;
        const float* b2 = kb2 + (size_t)l * KD;
        for (int it = tid; it < 6 * 4 * 32; it += 256) {
            int lane_ = it & 31;
            int kt = (it >> 5) & 3;
            int nt = it >> 7;
            int g_ = lane_ >> 2, t_ = lane_ & 3;
            int n  = nt * 8 + g_;
            int k0 = kt * 8 + t_;
            bool ok = (n < HK);
            uint32 lo = f2tf(ok ? w1[k0 * HK + n] : 0.f);
            uint32 hi = f2tf(ok ? w1[(k0 + 4) * HK + n] : 0.f);
            B1f[it] = make_uint2(lo, hi);
        }
        for (int it = tid; it < 8 * 6 * 32; it += 256) {
            int lane_ = it & 31;
            int kt = (it >> 5) % 6;
            int nt = it / 192;
            int g_ = lane_ >> 2, t_ = lane_ & 3;
            int n  = nt * 8 + g_;
            int k0 = kt * 8 + t_, k1 = k0 + 4;
            uint32 lo = f2tf((k0 < HK) ? w2[k0 * KD + n] : 0.f);
            uint32 hi = f2tf((k1 < HK) ? w2[k1 * KD + n] : 0.f);
            B2f[it] = make_uint2(lo, hi);
        }
        if (tid < 48) sb1[tid] = (tid < HK) ? b1[tid] : 0.f;
        if (tid < 64) sb2[tid] = b2[tid];
    }
    __syncthreads();

    uint32* Hw = Hall + w * 832;

    for (int i = w; i < NE; i += 8) {
        const float* dbase = dists + ((size_t)(b * NE + i)) * NA * BASIS;
        float macc[16];
        #pragma unroll
        for (int r = 0; r < 16; ++r) macc[r] = 0.f;

        #pragma unroll
        for (int mt = 0; mt < 3; ++mt) {
            const int j0 = mt * 16 + g, j1 = j0 + 8;

            uint32 A1[4][4];
            #pragma unroll
            for (int kt = 0; kt < 4; ++kt) {
                int k0 = kt * 8 + t;
                float a0 = (j0 < NA) ? __ldg(dbase + j0 * BASIS + k0) : 0.f;
                float a1 = (j1 < NA) ? __ldg(dbase + j1 * BASIS + k0) : 0.f;
                float a2 = (j0 < NA) ? __ldg(dbase + j0 * BASIS + k0 + 4) : 0.f;
                float a3 = (j1 < NA) ? __ldg(dbase + j1 * BASIS + k0 + 4) : 0.f;
                A1[kt][0] = f2tf(a0); A1[kt][1] = f2tf(a1);
                A1[kt][2] = f2tf(a2); A1[kt][3] = f2tf(a3);
            }

            #pragma unroll
            for (int nt = 0; nt < 6; ++nt) {
                float2 bb = *reinterpret_cast<const float2*>(sb1 + nt * 8 + 2 * t);
                float d0 = bb.x, d1 = bb.y, d2 = bb.x, d3 = bb.y;
                const uint2* bp = B1f + nt * 128 + lane;
                #pragma unroll
                for (int kt = 0; kt < 4; ++kt) {
                    uint2 bf = bp[kt * 32];
                    mma8(d0, d1, d2, d3,
                         A1[kt][0], A1[kt][1], A1[kt][2], A1[kt][3],
                         bf.x, bf.y);
                }
                uint2 lo = make_uint2(f2tf(ssp(d0)), f2tf(ssp(d1)));
                uint2 hi = make_uint2(f2tf(ssp(d2)), f2tf(ssp(d3)));
                *reinterpret_cast<uint2*>(Hw + g * 52 + nt * 8 + 2 * t)       = lo;
                *reinterpret_cast<uint2*>(Hw + (g + 8) * 52 + nt * 8 + 2 * t) = hi;
            }
            __syncwarp();

            uint32 A2[6][4];
            #pragma unroll
            for (int kt = 0; kt < 6; ++kt) {
                A2[kt][0] = Hw[g * 52 + kt * 8 + t];
                A2[kt][1] = Hw[(g + 8) * 52 + kt * 8 + t];
                A2[kt][2] = Hw[g * 52 + kt * 8 + t + 4];
                A2[kt][3] = Hw[(g + 8) * 52 + kt * 8 + t + 4];
            }
            const float pm0 = (j0 != i) ? 1.f : 0.f;
            const float pm1 = (j1 != i) ? 1.f : 0.f;

            #pragma unroll
            for (int nt = 0; nt < 8; ++nt) {
                float2 bb = *reinterpret_cast<const float2*>(sb2 + nt * 8 + 2 * t);
                float d0 = bb.x, d1 = bb.y, d2 = bb.x, d3 = bb.y;
                const uint2* bp = B2f + nt * 192 + lane;
                #pragma unroll
                for (int kt = 0; kt < 6; ++kt) {
                    uint2 bf = bp[kt * 32];
                    mma8(d0, d1, d2, d3,
                         A2[kt][0], A2[kt][1], A2[kt][2], A2[kt][3],
                         bf.x, bf.y);
                }
                float2 z0 = *reinterpret_cast<const float2*>(zsv + j0 * 72 + nt * 8 + 2 * t);
                float2 z1 = *reinterpret_cast<const float2*>(zsv + j1 * 72 + nt * 8 + 2 * t);
                macc[2 * nt]     += pm0 * d0 * z0.x + pm1 * d2 * z1.x;
                macc[2 * nt + 1] += pm0 * d1 * z0.y + pm1 * d3 * z1.y;
            }
            __syncwarp();
        }

        #pragma unroll
        for (int r = 0; r < 16; ++r) {
            macc[r] += __shfl_xor_sync(0xffffffffu, macc[r], 4);
            macc[r] += __shfl_xor_sync(0xffffffffu, macc[r], 8);
            macc[r] += __shfl_xor_sync(0xffffffffu, macc[r], 16);
        }
        if (g == 0) {
            float* mp = g_msg + ((size_t)(b * NE + i)) * KD;
            #pragma unroll
            for (int nt = 0; nt < 8; ++nt)
                *reinterpret_cast<float2*>(mp + nt * 8 + 2 * t) =
                    make_float2(macc[2 * nt], macc[2 * nt + 1]);
        }
    }
}

// ---------------------------------------------------------------------------
// k_out — tf32 MMA version.
// smem (floats):
//   smsg [0,2176)     32 rows x stride 68 (rows>=30 zero)
//   H    [2176,5376)  32 rows x stride 100 (tf32 bits)
//   sb1  [5376,5472)  96 (pad 0 past 91)
//   sb2  [5472,5600)  128
//   B1f  [5600,11744)   uint2[12nt][8kt][32lane]
//   B2f  [11744,24032)  uint2[16nt][12kt][32lane]
// ---------------------------------------------------------------------------
#define KO_TOTAL_F 24032
#define KO_BYTES   (KO_TOTAL_F * 4)

__global__ void __launch_bounds__(256) k_out(const float* __restrict__ ow1,
                                             const float* __restrict__ ob1,
                                             const float* __restrict__ ow2,
                                             const float* __restrict__ ob2,
                                             int l, float* __restrict__ xs_out) {
    extern __shared__ float smo[];
    float*  smsg = smo;
    uint32* Hs   = reinterpret_cast<uint32*>(smo + 2176);
    float*  sb1  = smo + 5376;
    float*  sb2  = smo + 5472;
    uint2*  B1f  = reinterpret_cast<uint2*>(smo + 5600);
    uint2*  B2f  = reinterpret_cast<uint2*>(smo + 11744);

    const int b = blockIdx.x, tid = threadIdx.x;
    const int w = tid >> 5, lane = tid & 31;
    const int g = lane >> 2, t = lane & 3;
    const float* W1 = ow1 + (size_t)l * KD * HO;
    const float* B1 = ob1 + (size_t)l * HO;
    const float* W2 = ow2 + (size_t)l * HO * ED;
    const float* B2 = ob2 + (size_t)l * ED;

    // ---- staging ----
    {
        const float* mg = g_msg + (size_t)b * NE * KD;
        for (int it = tid; it < 32 * 64; it += 256) {
            int r = it >> 6, c = it & 63;
            smsg[r * 68 + c] = (r < NE) ? mg[r * 64 + c] : 0.f;
        }
        for (int it = tid; it < 12 * 8 * 32; it += 256) {
            int lane_ = it & 31;
            int kt = (it >> 5) & 7;
            int nt = it >> 8;
            int g_ = lane_ >> 2, t_ = lane_ & 3;
            int n  = nt * 8 + g_;
            int k0 = kt * 8 + t_;
            bool ok = (n < HO);
            uint32 lo = f2tf(ok ? W1[k0 * HO + n] : 0.f);
            uint32 hi = f2tf(ok ? W1[(k0 + 4) * HO + n] : 0.f);
            B1f[it] = make_uint2(lo, hi);
        }
        for (int it = tid; it < 16 * 12 * 32; it += 256) {
            int lane_ = it & 31;
            int kt = (it >> 5) % 12;
            int nt = it / 384;
            int g_ = lane_ >> 2, t_ = lane_ & 3;
            int n  = nt * 8 + g_;
            int k0 = kt * 8 + t_;
            uint32 lo = f2tf((k0 < HO) ? W2[k0 * ED + n] : 0.f);
            uint32 hi = f2tf((k0 + 4 < HO) ? W2[(k0 + 4) * ED + n] : 0.f);
            B2f[it] = make_uint2(lo, hi);
        }
        if (tid < 96)  sb1[tid] = (tid < HO) ? B1[tid] : 0.f;
        if (tid < 128) sb2[tid] = B2[tid];
    }
    __syncthreads();

    // ---- GEMM1: H = ssp(msg @ W1 + b1); warps cover nt = w, w+8 ----
    #pragma unroll
    for (int mt = 0; mt < 2; ++mt) {
        uint32 A1[8][4];
        #pragma unroll
        for (int kt = 0; kt < 8; ++kt) {
            int r0 = (mt * 16 + g) * 68, r1 = (mt * 16 + g + 8) * 68;
            int c = kt * 8 + t;
            A1[kt][0] = f2tf(smsg[r0 + c]);
            A1[kt][1] = f2tf(smsg[r1 + c]);
            A1[kt][2] = f2tf(smsg[r0 + c + 4]);
            A1[kt][3] = f2tf(smsg[r1 + c + 4]);
        }
        #pragma unroll
        for (int rep = 0; rep < 2; ++rep) {
            int nt = w + 8 * rep;
            if (nt < 12) {
                float2 bb = *reinterpret_cast<const float2*>(sb1 + nt * 8 + 2 * t);
                float d0 = bb.x, d1 = bb.y, d2 = bb.x, d3 = bb.y;
                const uint2* bp = B1f + nt * 256 + lane;
                #pragma unroll
                for (int kt = 0; kt < 8; ++kt) {
                    uint2 bf = bp[kt * 32];
                    mma8(d0, d1, d2, d3,
                         A1[kt][0], A1[kt][1], A1[kt][2], A1[kt][3],
                         bf.x, bf.y);
                }
                int c = nt * 8 + 2 * t;
                *reinterpret_cast<uint2*>(Hs + (mt * 16 + g) * 100 + c) =
                    make_uint2(f2tf(ssp(d0)), f2tf(ssp(d1)));
                *reinterpret_cast<uint2*>(Hs + (mt * 16 + g + 8) * 100 + c) =
                    make_uint2(f2tf(ssp(d2)), f2tf(ssp(d3)));
            }
        }
    }
    __syncthreads();

    // ---- GEMM2 + residual: out = xs + H @ W2 + b2; warp covers nt = 2w, 2w+1 ----
    #pragma unroll
    for (int mt = 0; mt < 2; ++mt) {
        uint32 A2[12][4];
        #pragma unroll
        for (int kt = 0; kt < 12; ++kt) {
            int r0 = (mt * 16 + g) * 100, r1 = (mt * 16 + g + 8) * 100;
            int c = kt * 8 + t;
            A2[kt][0] = Hs[r0 + c];
            A2[kt][1] = Hs[r1 + c];
            A2[kt][2] = Hs[r0 + c + 4];
            A2[kt][3] = Hs[r1 + c + 4];
        }
        #pragma unroll
        for (int idx = 0; idx < 2; ++idx) {
            int nt = 2 * w + idx;
            float2 bb = *reinterpret_cast<const float2*>(sb2 + nt * 8 + 2 * t);
            float d0 = bb.x, d1 = bb.y, d2 = bb.x, d3 = bb.y;
            const uint2* bp = B2f + nt * 384 + lane;
            #pragma unroll
            for (int kt = 0; kt < 12; ++kt) {
                uint2 bf = bp[kt * 32];
                mma8(d0, d1, d2, d3,
                     A2[kt][0], A2[kt][1], A2[kt][2], A2[kt][3],
                     bf.x, bf.y);
            }
            int r0 = mt * 16 + g, r1 = r0 + 8;
            int c = nt * 8 + 2 * t;
            if (r0 < NE) {
                size_t o = ((size_t)(b * NE + r0)) * ED + c;
                float2 xv = *reinterpret_cast<const float2*>(g_xs + o);
                *reinterpret_cast<float2*>(xs_out + o) =
                    make_float2(xv.x + d0, xv.y + d1);
            }
            if (r1 < NE) {
                size_t o = ((size_t)(b * NE + r1)) * ED + c;
                float2 xv = *reinterpret_cast<const float2*>(g_xs + o);
                *reinterpret_cast<float2*>(xs_out + o) =
                    make_float2(xv.x + d2, xv.y + d3);
            }
        }
    }
}

// ---------------------------------------------------------------------------
extern "C" void kernel_launch(void* const* d_in, const int* in_sizes, int n_in,
                              void* d_out, int out_size) {
    const float* dists    = (const float*)d_in[0];
    const float* emb_elec = (const float*)d_in[1];
    const float* emb_nuc  = (const float*)d_in[2];
    const float* kw1      = (const float*)d_in[3];
    const float* kb1      = (const float*)d_in[4];
    const float* kw2      = (const float*)d_in[5];
    const float* kb2      = (const float*)d_in[6];
    const float* eiw      = (const float*)d_in[7];
    const float* ow1      = (const float*)d_in[8];
    const float* ob1      = (const float*)d_in[9];
    const float* ow2      = (const float*)d_in[10];
    const float* ob2      = (const float*)d_in[11];
    float* out = (float*)d_out;

    static int configured = 0;
    if (!configured) {
        cudaFuncSetAttribute(k_msg, cudaFuncAttributeMaxDynamicSharedMemorySize, MS_BYTES);
        cudaFuncSetAttribute(k_out, cudaFuncAttributeMaxDynamicSharedMemorySize, KO_BYTES);
        configured = 1;
    }
    void* xsptr = nullptr;
    cudaGetSymbolAddress(&xsptr, g_xs);

    k_init<<<4096, 256>>>(emb_elec);
    for (int l = 0; l < NL; ++l) {
        k_msg<<<NB, 256, MS_BYTES>>>(dists, emb_nuc, eiw, kw1, kb1, kw2, kb2, l);
        float* xs_out = (l == NL - 1) ? out : (float*)xsptr;
        k_out<<<NB, 256, KO_BYTES>>>(ow1, ob1, ow2, ob2, l, xs_out);
    }
}

// round 10
// speedup vs baseline: 1.8876x; 1.1559x over previous
#include <cuda_runtime.h>

#define NB    2048
#define NE    30
#define NA    38
#define NN    8
#define BASIS 32
#define KD    64
#define ED    128
#define HK    45
#define HO    91
#define NL    3

typedef unsigned long long ull;
typedef unsigned int uint32;

__device__ float g_xs [NB * NE * ED];

// Prepacked tf32 B-fragments (fragment order), filled once by k_prepack.
__device__ uint2 g_B1f[NL][6 * 4 * 32];     // msg w1  [nt6][kt4][lane]
__device__ uint2 g_B2f[NL][8 * 6 * 32];     // msg w2  [nt8][kt6][lane]
__device__ uint2 g_B1o[NL][12 * 8 * 32];    // out W1  [nt12][kt8][lane]
__device__ uint2 g_B2o[NL][16 * 12 * 32];   // out W2  [nt16][kt12][lane]

__device__ __forceinline__ float ssp(float x) {
    float t = __expf(-fabsf(x));
    return fmaxf(x, 0.f) + __logf(1.f + t) - 0.69314718055994530942f;
}
__device__ __forceinline__ ull ffma2(ull a, ull b, ull c) {
    ull d; asm("fma.rn.f32x2 %0, %1, %2, %3;" : "=l"(d) : "l"(a), "l"(b), "l"(c));
    return d;
}
__device__ __forceinline__ ull pack2(float x, float y) {
    ull r; asm("mov.b64 %0, {%1, %2};" : "=l"(r) : "f"(x), "f"(y)); return r;
}
__device__ __forceinline__ ull dup2(float x) { return pack2(x, x); }
__device__ __forceinline__ float2 unpack2(ull v) {
    float2 r; asm("mov.b64 {%0, %1}, %2;" : "=f"(r.x), "=f"(r.y) : "l"(v)); return r;
}
__device__ __forceinline__ ull ldsu64(const float* p) {
    return *reinterpret_cast<const ull*>(p);
}
__device__ __forceinline__ void sts2(float* p, float x, float y) {
    *reinterpret_cast<float2*>(p) = make_float2(x, y);
}
__device__ __forceinline__ uint32 f2tf(float x) {
    uint32 u; asm("cvt.rna.tf32.f32 %0, %1;" : "=r"(u) : "f"(x)); return u;
}
__device__ __forceinline__ void mma8(float& d0, float& d1, float& d2, float& d3,
                                     uint32 a0, uint32 a1, uint32 a2, uint32 a3,
                                     uint32 b0, uint32 b1) {
    asm volatile(
        "mma.sync.aligned.m16n8k8.row.col.f32.tf32.tf32.f32 "
        "{%0,%1,%2,%3},{%4,%5,%6,%7},{%8,%9},{%0,%1,%2,%3};"
        : "+f"(d0), "+f"(d1), "+f"(d2), "+f"(d3)
        : "r"(a0), "r"(a1), "r"(a2), "r"(a3), "r"(b0), "r"(b1));
}

__global__ void k_init(const float* __restrict__ emb_elec) {
    const int total = NB * NE * ED;
    for (int idx = blockIdx.x * blockDim.x + threadIdx.x; idx < total;
         idx += gridDim.x * blockDim.x) {
        int d = idx % ED, i = (idx / ED) % NE;
        g_xs[idx] = emb_elec[i * ED + d];
    }
}

// ---------------------------------------------------------------------------
// One-time fragment prepack: block l handles layer l.
// ---------------------------------------------------------------------------
__global__ void k_prepack(const float* __restrict__ kw1,
                          const float* __restrict__ kw2,
                          const float* __restrict__ ow1,
                          const float* __restrict__ ow2) {
    const int l = blockIdx.x, tid = threadIdx.x;
    const float* w1 = kw1 + (size_t)l * BASIS * HK;
    const float* w2 = kw2 + (size_t)l * HK * KD;
    const float* W1 = ow1 + (size_t)l * KD * HO;
    const float* W2 = ow2 + (size_t)l * HO * ED;

    for (int it = tid; it < 6 * 4 * 32; it += 256) {
        int lane_ = it & 31;
        int kt = (it >> 5) & 3;
        int nt = it >> 7;
        int g_ = lane_ >> 2, t_ = lane_ & 3;
        int n  = nt * 8 + g_;
        int k0 = kt * 8 + t_;
        bool ok = (n < HK);
        g_B1f[l][it] = make_uint2(f2tf(ok ? w1[k0 * HK + n] : 0.f),
                                  f2tf(ok ? w1[(k0 + 4) * HK + n] : 0.f));
    }
    for (int it = tid; it < 8 * 6 * 32; it += 256) {
        int lane_ = it & 31;
        int kt = (it >> 5) % 6;
        int nt = it / 192;
        int g_ = lane_ >> 2, t_ = lane_ & 3;
        int n  = nt * 8 + g_;
        int k0 = kt * 8 + t_, k1 = k0 + 4;
        g_B2f[l][it] = make_uint2(f2tf((k0 < HK) ? w2[k0 * KD + n] : 0.f),
                                  f2tf((k1 < HK) ? w2[k1 * KD + n] : 0.f));
    }
    for (int it = tid; it < 12 * 8 * 32; it += 256) {
        int lane_ = it & 31;
        int kt = (it >> 5) & 7;
        int nt = it >> 8;
        int g_ = lane_ >> 2, t_ = lane_ & 3;
        int n  = nt * 8 + g_;
        int k0 = kt * 8 + t_;
        bool ok = (n < HO);
        g_B1o[l][it] = make_uint2(f2tf(ok ? W1[k0 * HO + n] : 0.f),
                                  f2tf(ok ? W1[(k0 + 4) * HO + n] : 0.f));
    }
    for (int it = tid; it < 16 * 12 * 32; it += 256) {
        int lane_ = it & 31;
        int kt = (it >> 5) % 12;
        int nt = it / 384;
        int g_ = lane_ >> 2, t_ = lane_ & 3;
        int n  = nt * 8 + g_;
        int k0 = kt * 8 + t_;
        g_B2o[l][it] = make_uint2(f2tf((k0 < HO) ? W2[k0 * ED + n] : 0.f),
                                  f2tf((k0 + 4 < HO) ? W2[(k0 + 4) * ED + n] : 0.f));
    }
}

// ---------------------------------------------------------------------------
// k_layer = k_msg + fused k_out.
// smem (floats):
//   zsv   [0,3456)       zs[j][c], j 0..47 (38..47 zero), stride 72
//   smsg  [3456,5632)    32 rows x stride 68 (rows>=30 zero)
//   scratch [5632,17664) (12032 floats)
//     phase1: eiwv 8192 @scratch | xs2 3840 @scratch+8192
//     phase2: B1f uint2[768] (1536 f) @scratch
//             B2f uint2[1536] (3072 f) @scratch+1536
//             H per warp 16x52 (832 f)  @scratch+4608 (+w*832)
//     out:    Hs 32x100 (3200 f) @scratch
//   sb1 [17664,17712) | sb2 [17712,17776) | sb1o [17776,17872) | sb2o [17872,18000)
// ---------------------------------------------------------------------------
#define MS_TOTAL_F 18000
#define MS_BYTES   (MS_TOTAL_F * 4)

__global__ void __launch_bounds__(256, 3) k_layer(
        const float* __restrict__ dists,
        const float* __restrict__ emb_nuc,
        const float* __restrict__ eiw,
        const float* __restrict__ kb1,
        const float* __restrict__ kb2,
        const float* __restrict__ ob1,
        const float* __restrict__ ob2,
        int l, float* __restrict__ xs_out) {
    extern __shared__ float sm[];
    float*  zsv     = sm;
    float*  smsg    = sm + 3456;
    float*  scratch = sm + 5632;
    float*  eiwv    = scratch;
    float*  xs2     = scratch + 8192;
    uint2*  B1f     = reinterpret_cast<uint2*>(scratch);
    uint2*  B2f     = reinterpret_cast<uint2*>(scratch + 1536);
    uint32* Hall    = reinterpret_cast<uint32*>(scratch + 4608);
    uint32* Hs      = reinterpret_cast<uint32*>(scratch);
    float*  sb1     = sm + 17664;
    float*  sb2     = sm + 17712;
    float*  sb1o    = sm + 17776;
    float*  sb2o    = sm + 17872;

    const int b = blockIdx.x, tid = threadIdx.x;
    const int w = tid >> 5, lane = tid & 31;
    const int g = lane >> 2, t = lane & 3;

    // ---- phase 1a: stage eiw + xs, nuclear zs, pads, biases ----
    {
        const float* W = eiw + (size_t)l * ED * KD;
        for (int it = tid; it < ED * 32; it += 256) {
            int q = it >> 5, c = it & 31;
            sts2(eiwv + 2 * it, W[q * KD + c], W[q * KD + c + 32]);
        }
        const float* xsb = g_xs + (size_t)b * NE * ED;
        for (int it = tid; it < 15 * ED; it += 256) {
            int p = it >> 7, q = it & 127;
            sts2(xs2 + 2 * it, xsb[(2 * p) * ED + q], xsb[(2 * p + 1) * ED + q]);
        }
        for (int idx = tid; idx < NN * KD; idx += 256) {
            int n = idx >> 6, c = idx & 63;
            zsv[(NE + n) * 72 + c] = emb_nuc[n * KD + c];
        }
        for (int idx = tid; idx < 10 * 64; idx += 256) {
            int r = idx >> 6, c = idx & 63;
            zsv[(38 + r) * 72 + c] = 0.f;
        }
        // smsg pad rows 30,31
        for (int idx = tid; idx < 2 * 68; idx += 256)
            smsg[30 * 68 + idx] = 0.f;
        if (tid < 48)  sb1[tid]  = (tid < HK) ? kb1[l * HK + tid] : 0.f;
        if (tid < 64)  sb2[tid]  = kb2[l * KD + tid];
        if (tid < 96)  sb1o[tid] = (tid < HO) ? ob1[l * HO + tid] : 0.f;
        if (tid < 128) sb2o[tid] = ob2[l * ED + tid];
    }
    __syncthreads();

    // ---- phase 1b: electron zs = xs @ eiw (f32x2 over electron pairs) ----
    for (int p = w; p < 15; p += 8) {
        ull acc0 = 0ull, acc1 = 0ull;
        const float* xrow = xs2 + p * 256;
        #pragma unroll 8
        for (int q = 0; q < ED; ++q) {
            ull x2 = ldsu64(xrow + 2 * q);
            float2 wf = unpack2(ldsu64(eiwv + (q * 32 + lane) * 2));
            acc0 = ffma2(x2, dup2(wf.x), acc0);
            acc1 = ffma2(x2, dup2(wf.y), acc1);
        }
        float2 a0 = unpack2(acc0), a1 = unpack2(acc1);
        zsv[(2 * p) * 72 + lane]          = a0.x;
        zsv[(2 * p + 1) * 72 + lane]      = a0.y;
        zsv[(2 * p) * 72 + lane + 32]     = a1.x;
        zsv[(2 * p + 1) * 72 + lane + 32] = a1.y;
    }
    __syncthreads();

    // ---- phase 2a: copy prepacked msg B-fragments into smem ----
    {
        const uint4* s1 = reinterpret_cast<const uint4*>(g_B1f[l]);
        uint4* d1 = reinterpret_cast<uint4*>(B1f);
        for (int it = tid; it < 384; it += 256) d1[it] = s1[it];
        const uint4* s2 = reinterpret_cast<const uint4*>(g_B2f[l]);
        uint4* d2 = reinterpret_cast<uint4*>(B2f);
        for (int it = tid; it < 768; it += 256) d2[it] = s2[it];
    }
    __syncthreads();

    uint32* Hw = Hall + w * 832;

    // ---- main loop: pair MLP + j-sum -> smsg ----
    for (int i = w; i < NE; i += 8) {
        const float* dbase = dists + ((size_t)(b * NE + i)) * NA * BASIS;
        float macc[16];
        #pragma unroll
        for (int r = 0; r < 16; ++r) macc[r] = 0.f;

        #pragma unroll
        for (int mt = 0; mt < 3; ++mt) {
            const int j0 = mt * 16 + g, j1 = j0 + 8;

            uint32 A1[4][4];
            #pragma unroll
            for (int kt = 0; kt < 4; ++kt) {
                int k0 = kt * 8 + t;
                float a0 = (j0 < NA) ? __ldg(dbase + j0 * BASIS + k0) : 0.f;
                float a1 = (j1 < NA) ? __ldg(dbase + j1 * BASIS + k0) : 0.f;
                float a2 = (j0 < NA) ? __ldg(dbase + j0 * BASIS + k0 + 4) : 0.f;
                float a3 = (j1 < NA) ? __ldg(dbase + j1 * BASIS + k0 + 4) : 0.f;
                A1[kt][0] = f2tf(a0); A1[kt][1] = f2tf(a1);
                A1[kt][2] = f2tf(a2); A1[kt][3] = f2tf(a3);
            }

            #pragma unroll
            for (int nt = 0; nt < 6; ++nt) {
                float2 bb = *reinterpret_cast<const float2*>(sb1 + nt * 8 + 2 * t);
                float d0 = bb.x, d1 = bb.y, d2 = bb.x, d3 = bb.y;
                const uint2* bp = B1f + nt * 128 + lane;
                #pragma unroll
                for (int kt = 0; kt < 4; ++kt) {
                    uint2 bf = bp[kt * 32];
                    mma8(d0, d1, d2, d3,
                         A1[kt][0], A1[kt][1], A1[kt][2], A1[kt][3],
                         bf.x, bf.y);
                }
                uint2 lo = make_uint2(f2tf(ssp(d0)), f2tf(ssp(d1)));
                uint2 hi = make_uint2(f2tf(ssp(d2)), f2tf(ssp(d3)));
                *reinterpret_cast<uint2*>(Hw + g * 52 + nt * 8 + 2 * t)       = lo;
                *reinterpret_cast<uint2*>(Hw + (g + 8) * 52 + nt * 8 + 2 * t) = hi;
            }
            __syncwarp();

            uint32 A2[6][4];
            #pragma unroll
            for (int kt = 0; kt < 6; ++kt) {
                A2[kt][0] = Hw[g * 52 + kt * 8 + t];
                A2[kt][1] = Hw[(g + 8) * 52 + kt * 8 + t];
                A2[kt][2] = Hw[g * 52 + kt * 8 + t + 4];
                A2[kt][3] = Hw[(g + 8) * 52 + kt * 8 + t + 4];
            }
            const float pm0 = (j0 != i) ? 1.f : 0.f;
            const float pm1 = (j1 != i) ? 1.f : 0.f;

            #pragma unroll
            for (int nt = 0; nt < 8; ++nt) {
                float2 bb = *reinterpret_cast<const float2*>(sb2 + nt * 8 + 2 * t);
                float d0 = bb.x, d1 = bb.y, d2 = bb.x, d3 = bb.y;
                const uint2* bp = B2f + nt * 192 + lane;
                #pragma unroll
                for (int kt = 0; kt < 6; ++kt) {
                    uint2 bf = bp[kt * 32];
                    mma8(d0, d1, d2, d3,
                         A2[kt][0], A2[kt][1], A2[kt][2], A2[kt][3],
                         bf.x, bf.y);
                }
                float2 z0 = *reinterpret_cast<const float2*>(zsv + j0 * 72 + nt * 8 + 2 * t);
                float2 z1 = *reinterpret_cast<const float2*>(zsv + j1 * 72 + nt * 8 + 2 * t);
                macc[2 * nt]     += pm0 * d0 * z0.x + pm1 * d2 * z1.x;
                macc[2 * nt + 1] += pm0 * d1 * z0.y + pm1 * d3 * z1.y;
            }
            __syncwarp();
        }

        #pragma unroll
        for (int r = 0; r < 16; ++r) {
            macc[r] += __shfl_xor_sync(0xffffffffu, macc[r], 4);
            macc[r] += __shfl_xor_sync(0xffffffffu, macc[r], 8);
            macc[r] += __shfl_xor_sync(0xffffffffu, macc[r], 16);
        }
        if (g == 0) {
            #pragma unroll
            for (int nt = 0; nt < 8; ++nt)
                sts2(smsg + i * 68 + nt * 8 + 2 * t, macc[2 * nt], macc[2 * nt + 1]);
        }
    }
    __syncthreads();   // smsg complete; scratch (B1f/B2f/H) now dead

    // ---- out GEMM1: Hs = ssp(msg @ W1 + b1); warp covers nt = w, w+8 ----
    #pragma unroll
    for (int mt = 0; mt < 2; ++mt) {
        int r0 = (mt * 16 + g) * 68, r1 = (mt * 16 + g + 8) * 68;
        #pragma unroll
        for (int rep = 0; rep < 2; ++rep) {
            int nt = w + 8 * rep;
            if (nt < 12) {
                float2 bb = *reinterpret_cast<const float2*>(sb1o + nt * 8 + 2 * t);
                float d0 = bb.x, d1 = bb.y, d2 = bb.x, d3 = bb.y;
                const uint2* bp = g_B1o[l] + nt * 256 + lane;
                #pragma unroll
                for (int kt = 0; kt < 8; ++kt) {
                    int c = kt * 8 + t;
                    uint32 a0 = f2tf(smsg[r0 + c]);
                    uint32 a1 = f2tf(smsg[r1 + c]);
                    uint32 a2 = f2tf(smsg[r0 + c + 4]);
                    uint32 a3 = f2tf(smsg[r1 + c + 4]);
                    uint2 bf = __ldg(bp + kt * 32);
                    mma8(d0, d1, d2, d3, a0, a1, a2, a3, bf.x, bf.y);
                }
                int c = nt * 8 + 2 * t;
                *reinterpret_cast<uint2*>(Hs + (mt * 16 + g) * 100 + c) =
                    make_uint2(f2tf(ssp(d0)), f2tf(ssp(d1)));
                *reinterpret_cast<uint2*>(Hs + (mt * 16 + g + 8) * 100 + c) =
                    make_uint2(f2tf(ssp(d2)), f2tf(ssp(d3)));
            }
        }
    }
    __syncthreads();

    // ---- out GEMM2 + residual: xs_out = xs + Hs @ W2 + b2; nt = 2w, 2w+1 ----
    #pragma unroll
    for (int mt = 0; mt < 2; ++mt) {
        int r0 = (mt * 16 + g) * 100, r1 = (mt * 16 + g + 8) * 100;
        int e0 = mt * 16 + g, e1 = e0 + 8;
        #pragma unroll
        for (int idx = 0; idx < 2; ++idx) {
            int nt = 2 * w + idx;
            float2 bb = *reinterpret_cast<const float2*>(sb2o + nt * 8 + 2 * t);
            float d0 = bb.x, d1 = bb.y, d2 = bb.x, d3 = bb.y;
            const uint2* bp = g_B2o[l] + nt * 384 + lane;
            #pragma unroll
            for (int kt = 0; kt < 12; ++kt) {
                int c = kt * 8 + t;
                uint2 bf = __ldg(bp + kt * 32);
                mma8(d0, d1, d2, d3,
                     Hs[r0 + c], Hs[r1 + c], Hs[r0 + c + 4], Hs[r1 + c + 4],
                     bf.x, bf.y);
            }
            int c = nt * 8 + 2 * t;
            if (e0 < NE) {
                size_t o = ((size_t)(b * NE + e0)) * ED + c;
                float2 xv = *reinterpret_cast<const float2*>(g_xs + o);
                *reinterpret_cast<float2*>(xs_out + o) =
                    make_float2(xv.x + d0, xv.y + d1);
            }
            if (e1 < NE) {
                size_t o = ((size_t)(b * NE + e1)) * ED + c;
                float2 xv = *reinterpret_cast<const float2*>(g_xs + o);
                *reinterpret_cast<float2*>(xs_out + o) =
                    make_float2(xv.x + d2, xv.y + d3);
            }
        }
    }
}

// ---------------------------------------------------------------------------
extern "C" void kernel_launch(void* const* d_in, const int* in_sizes, int n_in,
                              void* d_out, int out_size) {
    const float* dists    = (const float*)d_in[0];
    const float* emb_elec = (const float*)d_in[1];
    const float* emb_nuc  = (const float*)d_in[2];
    const float* kw1      = (const float*)d_in[3];
    const float* kb1      = (const float*)d_in[4];
    const float* kw2      = (const float*)d_in[5];
    const float* kb2      = (const float*)d_in[6];
    const float* eiw      = (const float*)d_in[7];
    const float* ow1      = (const float*)d_in[8];
    const float* ob1      = (const float*)d_in[9];
    const float* ow2      = (const float*)d_in[10];
    const float* ob2      = (const float*)d_in[11];
    float* out = (float*)d_out;

    static int configured = 0;
    if (!configured) {
        cudaFuncSetAttribute(k_layer, cudaFuncAttributeMaxDynamicSharedMemorySize, MS_BYTES);
        configured = 1;
    }
    void* xsptr = nullptr;
    cudaGetSymbolAddress(&xsptr, g_xs);

    k_init<<<4096, 256>>>(emb_elec);
    k_prepack<<<NL, 256>>>(kw1, kw2, ow1, ow2);
    for (int l = 0; l < NL; ++l) {
        float* xs_out = (l == NL - 1) ? out : (float*)xsptr;
        k_layer<<<NB, 256, MS_BYTES>>>(dists, emb_nuc, eiw, kb1, kb2, ob1, ob2,
                                       l, xs_out);
    }
}